// round 10
// baseline (speedup 1.0000x reference)
#include <cuda_runtime.h>
#include <cuda_fp16.h>
#include <cstdint>

#define CC    64
#define CC2   32
#define TT    8
#define PP    2304
#define NBT   16
#define NTILE 18
#define VROWS 72

typedef unsigned int u32;

__device__ __half g_q [NBT * PP * CC2];      // theta * scale * log2e, [bt][p][32]
__device__ __half g_k [NBT * PP * CC2];      // phi,                  [bt][p][32]
__device__ __half g_vt[NBT * VROWS * PP];    // (out_w @ x)^T + ones row, [bt][o][p]

__device__ __forceinline__ u32 smem_u32(const void* p){
    u32 a; asm("{ .reg .u64 t; cvta.to.shared.u64 t, %1; cvt.u32.u64 %0, t; }":"=r"(a):"l"(p)); return a;
}

#define LDSM4(r, a) \
    asm volatile("ldmatrix.sync.aligned.m8n8.x4.shared.b16 {%0,%1,%2,%3}, [%4];" \
        : "=r"((r)[0]),"=r"((r)[1]),"=r"((r)[2]),"=r"((r)[3]) : "r"(a))

#define MMAF16(d, a0, a1, a2, a3, b0, b1) \
    asm volatile("mma.sync.aligned.m16n8k16.row.col.f32.f16.f16.f32 " \
        "{%0,%1,%2,%3}, {%4,%5,%6,%7}, {%8,%9}, {%0,%1,%2,%3};" \
        : "+f"((d)[0]),"+f"((d)[1]),"+f"((d)[2]),"+f"((d)[3]) \
        : "r"(a0),"r"(a1),"r"(a2),"r"(a3), "r"(b0),"r"(b1))

// f16-accumulate variant: D/C are 2x b32 (f16x2); layout == A-fragment layout.
#define MMAF16H(d, a0, a1, a2, a3, b0, b1) \
    asm volatile("mma.sync.aligned.m16n8k16.row.col.f16.f16.f16.f16 " \
        "{%0,%1}, {%2,%3,%4,%5}, {%6,%7}, {%0,%1};" \
        : "+r"((d)[0]),"+r"((d)[1]) \
        : "r"(a0),"r"(a1),"r"(a2),"r"(a3), "r"(b0),"r"(b1))

#define CP16(dst, src) \
    asm volatile("cp.async.cg.shared.global [%0], [%1], 16;" :: "r"(dst), "l"(src))
#define CP_COMMIT() asm volatile("cp.async.commit_group;" ::: "memory")
#define CP_WAIT0()  asm volatile("cp.async.wait_group 0;" ::: "memory")

__device__ __forceinline__ u32 h2_u32(__half2 h){ return *(u32*)&h; }

// ---------------------------------------------------------------------------
// Kernel A: per-(b,t) projections, 8x8 outer-product register tiles; at the
// measured FFMA roofline. out_w folded into V; V transposed [o][p] with ones
// row at o=64. grid (16, 18), block 256.
// ---------------------------------------------------------------------------
#define XS_S 132
__global__ void __launch_bounds__(256)
prep_kernel(const float* __restrict__ x_in,
            const float* __restrict__ thw,
            const float* __restrict__ phw,
            const float* __restrict__ ow) {
    extern __shared__ float sm[];
    float* xs = sm;               // [64][132] : x[c][p_local]
    float* wt = sm + CC * XS_S;   // [64][132] : W^T[c][r]

    const int bt = blockIdx.x, b = bt >> 3, t = bt & 7;
    const int p0g = blockIdx.y * 128;
    const int tid = threadIdx.x;

    for (int i = tid; i < CC * 128; i += 256) {
        int c = i >> 7, pl = i & 127;
        xs[c * XS_S + pl] = x_in[((b * CC + c) * TT + t) * PP + p0g + pl];
    }
    for (int i = tid; i < CC2 * CC; i += 256) {
        int o = i >> 6, c = i & 63;
        wt[c * XS_S + o]      = thw[t * CC2 * CC + i];
        wt[c * XS_S + 32 + o] = phw[t * CC2 * CC + i];
    }
    for (int i = tid; i < CC * CC; i += 256) {
        int o = i >> 6, c = i & 63;
        wt[c * XS_S + 64 + o] = ow[i];
    }
    __syncthreads();

    const int r0 = (tid >> 4) << 3;
    const int p0 = (tid & 15) << 3;

    float acc[8][8];
    #pragma unroll
    for (int u = 0; u < 8; ++u)
        #pragma unroll
        for (int j = 0; j < 8; ++j) acc[u][j] = 0.f;

    #pragma unroll 4
    for (int c = 0; c < CC; ++c) {
        float4 w0 = *(float4*)&wt[c * XS_S + r0];
        float4 w1 = *(float4*)&wt[c * XS_S + r0 + 4];
        float4 x0 = *(float4*)&xs[c * XS_S + p0];
        float4 x1 = *(float4*)&xs[c * XS_S + p0 + 4];
        float wv[8] = {w0.x,w0.y,w0.z,w0.w,w1.x,w1.y,w1.z,w1.w};
        float xv[8] = {x0.x,x0.y,x0.z,x0.w,x1.x,x1.y,x1.z,x1.w};
        #pragma unroll
        for (int u = 0; u < 8; ++u)
            #pragma unroll
            for (int j = 0; j < 8; ++j)
                acc[u][j] = fmaf(wv[u], xv[j], acc[u][j]);
    }

    const float s2 = 0.17677669529663689f * 1.4426950408889634f;

    if (r0 < CC2) {
        #pragma unroll
        for (int j = 0; j < 8; ++j) {
            uint4 hv;
            hv.x = h2_u32(__floats2half2_rn(acc[0][j]*s2, acc[1][j]*s2));
            hv.y = h2_u32(__floats2half2_rn(acc[2][j]*s2, acc[3][j]*s2));
            hv.z = h2_u32(__floats2half2_rn(acc[4][j]*s2, acc[5][j]*s2));
            hv.w = h2_u32(__floats2half2_rn(acc[6][j]*s2, acc[7][j]*s2));
            *(uint4*)&g_q[((size_t)bt * PP + p0g + p0 + j) * CC2 + r0] = hv;
        }
    } else if (r0 < 2 * CC2) {
        #pragma unroll
        for (int j = 0; j < 8; ++j) {
            uint4 hv;
            hv.x = h2_u32(__floats2half2_rn(acc[0][j], acc[1][j]));
            hv.y = h2_u32(__floats2half2_rn(acc[2][j], acc[3][j]));
            hv.z = h2_u32(__floats2half2_rn(acc[4][j], acc[5][j]));
            hv.w = h2_u32(__floats2half2_rn(acc[6][j], acc[7][j]));
            *(uint4*)&g_k[((size_t)bt * PP + p0g + p0 + j) * CC2 + r0 - CC2] = hv;
        }
    } else {
        #pragma unroll
        for (int u = 0; u < 8; ++u) {
            uint4 hv;
            hv.x = h2_u32(__floats2half2_rn(acc[u][0], acc[u][1]));
            hv.y = h2_u32(__floats2half2_rn(acc[u][2], acc[u][3]));
            hv.z = h2_u32(__floats2half2_rn(acc[u][4], acc[u][5]));
            hv.w = h2_u32(__floats2half2_rn(acc[u][6], acc[u][7]));
            *(uint4*)&g_vt[((size_t)bt * VROWS + r0 - 2 * CC2 + u) * PP + p0g + p0] = hv;
        }
    }

    if (tid < 128) {
        const int row = 64 + (tid >> 4), seg = tid & 15;
        const __half2 one2 = __floats2half2_rn(1.f, 1.f);
        const u32 fill = (row == 64) ? h2_u32(one2) : 0u;
        uint4 hv = make_uint4(fill, fill, fill, fill);
        *(uint4*)&g_vt[((size_t)bt * VROWS + row) * PP + p0g + seg * 8] = hv;
    }
}

// ---------------------------------------------------------------------------
// Kernel B: flash attention, M=256 per CTA (32 rows/warp in 2 row-groups),
// grid (9,16) = 144 CTAs = one wave. S/PV interleaved per 16-key step:
// LDSM K -> S-MMA(f16 acc) -> h2exp2 -> PV MMAs for those 16 keys.
// B-fragments (K,V) amortized over both row-groups. Row sums via ones column.
// smem: Q @0 (256x80B) | K0 @20480 | K1 @30720 | V0 @40960 | V1 @60544 (72x272B)
// Epilogue reuses smem as O^T [64][260] f32.
// ---------------------------------------------------------------------------
#define QK_STB  80
#define VT_STB  272
#define SMB_Q   0
#define SMB_K0  20480
#define SMB_K1  30720
#define SMB_V0  40960
#define SMB_V1  60544
#define SMB_END 80128
#define OT_S    260

__global__ void __launch_bounds__(256, 1)
flash_kernel(const float* __restrict__ x_in, float* __restrict__ out) {
    extern __shared__ char smem[];
    const u32 sb  = smem_u32(smem);
    const int tid  = threadIdx.x;
    const int w    = tid >> 5, lane = tid & 31;
    const int g    = lane >> 2, tq = lane & 3;
    const int lm   = lane >> 3, lr = lane & 7;
    const int bt   = blockIdx.y, b = bt >> 3, t = bt & 7;
    const int q0   = blockIdx.x * 256;

    const __half* gqb = &g_q[(size_t)bt * PP * CC2];
    const __half* gkb = &g_k[(size_t)bt * PP * CC2];
    const __half* gvb = &g_vt[(size_t)bt * VROWS * PP];

    // ---- initial stage: Q (256 rows) + K0 + V0 ----
    {
        #pragma unroll
        for (int j = 0; j < 4; ++j) {
            int idx = tid + j * 256;
            int row = idx >> 2, col = idx & 3;
            CP16(sb + SMB_Q + row * QK_STB + col * 16, gqb + (size_t)(q0 + row) * CC2 + col * 8);
        }
        #pragma unroll
        for (int j = 0; j < 2; ++j) {
            int idx = tid + j * 256;
            int row = idx >> 2, col = idx & 3;
            CP16(sb + SMB_K0 + row * QK_STB + col * 16, gkb + (size_t)row * CC2 + col * 8);
        }
        #pragma unroll
        for (int j = 0; j < 5; ++j) {
            int idx = tid + j * 256;
            if (idx < 1152) {
                int row = idx >> 4, col = idx & 15;
                CP16(sb + SMB_V0 + row * VT_STB + col * 16, gvb + (size_t)row * PP + col * 8);
            }
        }
    }
    CP_COMMIT(); CP_WAIT0();
    __syncthreads();

    // Q A-fragments: 2 row-groups (rows w*16 and 128 + w*16)
    u32 aq[2][2][4];
    #pragma unroll
    for (int r = 0; r < 2; ++r) {
        const u32 qb = sb + SMB_Q + (r * 128 + w * 16 + (lm & 1) * 8 + lr) * QK_STB + (lm >> 1) * 16;
        LDSM4(aq[r][0], qb);
        LDSM4(aq[r][1], qb + 32);
    }

    float o[2][9][4];
    #pragma unroll
    for (int r = 0; r < 2; ++r)
        #pragma unroll
        for (int i = 0; i < 9; ++i)
            #pragma unroll
            for (int j = 0; j < 4; ++j) o[r][i][j] = 0.f;

    const u32 kldb[2] = { sb + SMB_K0 + lr * QK_STB + lm * 16,
                          sb + SMB_K1 + lr * QK_STB + lm * 16 };
    const u32 vldb[2] = { sb + SMB_V0 + lr * VT_STB + lm * 16,
                          sb + SMB_V1 + lr * VT_STB + lm * 16 };

    for (int kt = 0; kt < NTILE; ++kt) {
        const int cb = kt & 1, nb = cb ^ 1;
        const bool more = (kt + 1 < NTILE);

        // prefetch next K/V tile into the other buffer
        if (more) {
            const int k0 = (kt + 1) * 128;
            const u32 kdst = sb + (nb ? SMB_K1 : SMB_K0);
            const u32 vdst = sb + (nb ? SMB_V1 : SMB_V0);
            #pragma unroll
            for (int j = 0; j < 2; ++j) {
                int idx = tid + j * 256;
                int row = idx >> 2, col = idx & 3;
                CP16(kdst + row * QK_STB + col * 16, gkb + (size_t)(k0 + row) * CC2 + col * 8);
            }
            #pragma unroll
            for (int j = 0; j < 5; ++j) {
                int idx = tid + j * 256;
                if (idx < 1152) {
                    int row = idx >> 4, col = idx & 15;
                    CP16(vdst + row * VT_STB + col * 16, gvb + (size_t)row * PP + k0 + col * 8);
                }
            }
            CP_COMMIT();
        }

        // ---- interleaved: per 16-key step, S(f16)->exp2 then PV ----
        #pragma unroll
        for (int kp = 0; kp < 4; ++kp) {
            u32 pf[2][4][2];
            #pragma unroll
            for (int i = 0; i < 4; ++i) {
                const int nf = kp * 4 + i;
                u32 kb[4];
                LDSM4(kb, kldb[cb] + nf * 8 * QK_STB);
                #pragma unroll
                for (int r = 0; r < 2; ++r) {
                    u32 d[2] = {0u, 0u};
                    MMAF16H(d, aq[r][0][0], aq[r][0][1], aq[r][0][2], aq[r][0][3], kb[0], kb[1]);
                    MMAF16H(d, aq[r][1][0], aq[r][1][1], aq[r][1][2], aq[r][1][3], kb[2], kb[3]);
                    pf[r][i][0] = h2_u32(h2exp2(*(__half2*)&d[0]));
                    pf[r][i][1] = h2_u32(h2exp2(*(__half2*)&d[1]));
                }
            }
            #pragma unroll
            for (int nf2 = 0; nf2 < 9; ++nf2) {
                u32 vb[4];
                LDSM4(vb, vldb[cb] + nf2 * 8 * VT_STB + kp * 64);
                #pragma unroll
                for (int r = 0; r < 2; ++r) {
                    MMAF16(o[r][nf2], pf[r][0][0], pf[r][0][1], pf[r][1][0], pf[r][1][1], vb[0], vb[1]);
                    MMAF16(o[r][nf2], pf[r][2][0], pf[r][2][1], pf[r][3][0], pf[r][3][1], vb[2], vb[3]);
                }
            }
        }

        CP_WAIT0();
        __syncthreads();
    }

    // ---- row sums from ones-column; normalize; transpose via smem ----
    const int qlead = lane & 28;
    float* ot = (float*)smem;
    #pragma unroll
    for (int r = 0; r < 2; ++r) {
        const float inv_lo = 1.f / __shfl_sync(0xffffffffu, o[r][8][0], qlead);
        const float inv_hi = 1.f / __shfl_sync(0xffffffffu, o[r][8][2], qlead);
        const int prow = r * 128 + w * 16 + g;
        #pragma unroll
        for (int nf2 = 0; nf2 < 8; ++nf2) {
            int oc = nf2 * 8 + 2 * tq;
            ot[(oc    ) * OT_S + prow    ] = o[r][nf2][0] * inv_lo;
            ot[(oc + 1) * OT_S + prow    ] = o[r][nf2][1] * inv_lo;
            ot[(oc    ) * OT_S + prow + 8] = o[r][nf2][2] * inv_hi;
            ot[(oc + 1) * OT_S + prow + 8] = o[r][nf2][3] * inv_hi;
        }
    }
    __syncthreads();

    // out[b, o, t, q0 + p] = O^T + residual (coalesced float4)
    {
        const int oc = tid >> 2, qt = tid & 3;
        const size_t gb = ((size_t)(b * CC + oc) * TT + t) * PP + q0 + qt * 64;
        const float* src = &ot[oc * OT_S + qt * 64];
        #pragma unroll
        for (int j = 0; j < 16; ++j) {
            float4 v = *(const float4*)&src[4 * j];
            float4 x = *(const float4*)&x_in[gb + 4 * j];
            v.x += x.x; v.y += x.y; v.z += x.z; v.w += x.w;
            *(float4*)&out[gb + 4 * j] = v;
        }
    }
}

// ---------------------------------------------------------------------------

extern "C" void kernel_launch(void* const* d_in, const int* in_sizes, int n_in,
                              void* d_out, int out_size) {
    const float* x_in = (const float*)d_in[0];
    const float* thw  = (const float*)d_in[1];
    const float* phw  = (const float*)d_in[2];
    const float* ow   = (const float*)d_in[3];
    float* out = (float*)d_out;

    const int prep_smem  = 2 * CC * XS_S * 4;  // 67584 B
    const int flash_smem = SMB_END;            // 80128 B

    cudaFuncSetAttribute(prep_kernel,  cudaFuncAttributeMaxDynamicSharedMemorySize, prep_smem);
    cudaFuncSetAttribute(flash_kernel, cudaFuncAttributeMaxDynamicSharedMemorySize, flash_smem);

    prep_kernel<<<dim3(NBT, PP / 128), 256, prep_smem>>>(x_in, thw, phw, ow);
    flash_kernel<<<dim3(PP / 256, NBT), 256, flash_smem>>>(x_in, out);
}

// round 12
// speedup vs baseline: 1.3377x; 1.3377x over previous
#include <cuda_runtime.h>
#include <cuda_fp16.h>
#include <cstdint>

#define CC    64
#define CC2   32
#define TT    8
#define PP    2304
#define NBT   16
#define NTILE 18
#define VROWS 72

typedef unsigned int u32;

__device__ __half g_q [NBT * PP * CC2];      // theta * scale * log2e, [bt][p][32]
__device__ __half g_k [NBT * PP * CC2];      // phi,                  [bt][p][32]
__device__ __half g_vt[NBT * VROWS * PP];    // (out_w @ x)^T + ones row, [bt][o][p]

__device__ __forceinline__ u32 smem_u32(const void* p){
    u32 a; asm("{ .reg .u64 t; cvta.to.shared.u64 t, %1; cvt.u32.u64 %0, t; }":"=r"(a):"l"(p)); return a;
}

#define LDSM4(r, a) \
    asm volatile("ldmatrix.sync.aligned.m8n8.x4.shared.b16 {%0,%1,%2,%3}, [%4];" \
        : "=r"((r)[0]),"=r"((r)[1]),"=r"((r)[2]),"=r"((r)[3]) : "r"(a))

#define MMAF16(d, a0, a1, a2, a3, b0, b1) \
    asm volatile("mma.sync.aligned.m16n8k16.row.col.f32.f16.f16.f32 " \
        "{%0,%1,%2,%3}, {%4,%5,%6,%7}, {%8,%9}, {%0,%1,%2,%3};" \
        : "+f"((d)[0]),"+f"((d)[1]),"+f"((d)[2]),"+f"((d)[3]) \
        : "r"(a0),"r"(a1),"r"(a2),"r"(a3), "r"(b0),"r"(b1))

// f16-accumulate variant: D/C are 2x b32 (f16x2); layout == A-fragment layout.
#define MMAF16H(d, a0, a1, a2, a3, b0, b1) \
    asm volatile("mma.sync.aligned.m16n8k16.row.col.f16.f16.f16.f16 " \
        "{%0,%1}, {%2,%3,%4,%5}, {%6,%7}, {%0,%1};" \
        : "+r"((d)[0]),"+r"((d)[1]) \
        : "r"(a0),"r"(a1),"r"(a2),"r"(a3), "r"(b0),"r"(b1))

#define CP16(dst, src) \
    asm volatile("cp.async.cg.shared.global [%0], [%1], 16;" :: "r"(dst), "l"(src))
#define CP_COMMIT() asm volatile("cp.async.commit_group;" ::: "memory")
#define CP_WAIT0()  asm volatile("cp.async.wait_group 0;" ::: "memory")

__device__ __forceinline__ u32 h2_u32(__half2 h){ return *(u32*)&h; }

// ---------------------------------------------------------------------------
// Kernel A: per-(b,t) projections, 8x8 outer-product register tiles; at the
// measured FFMA roofline. out_w folded into V; V transposed [o][p] with ones
// row at o=64. grid (16, 18), block 256.
// ---------------------------------------------------------------------------
#define XS_S 132
__global__ void __launch_bounds__(256)
prep_kernel(const float* __restrict__ x_in,
            const float* __restrict__ thw,
            const float* __restrict__ phw,
            const float* __restrict__ ow) {
    extern __shared__ float sm[];
    float* xs = sm;               // [64][132] : x[c][p_local]
    float* wt = sm + CC * XS_S;   // [64][132] : W^T[c][r]

    const int bt = blockIdx.x, b = bt >> 3, t = bt & 7;
    const int p0g = blockIdx.y * 128;
    const int tid = threadIdx.x;

    for (int i = tid; i < CC * 128; i += 256) {
        int c = i >> 7, pl = i & 127;
        xs[c * XS_S + pl] = x_in[((b * CC + c) * TT + t) * PP + p0g + pl];
    }
    for (int i = tid; i < CC2 * CC; i += 256) {
        int o = i >> 6, c = i & 63;
        wt[c * XS_S + o]      = thw[t * CC2 * CC + i];
        wt[c * XS_S + 32 + o] = phw[t * CC2 * CC + i];
    }
    for (int i = tid; i < CC * CC; i += 256) {
        int o = i >> 6, c = i & 63;
        wt[c * XS_S + 64 + o] = ow[i];
    }
    __syncthreads();

    const int r0 = (tid >> 4) << 3;
    const int p0 = (tid & 15) << 3;

    float acc[8][8];
    #pragma unroll
    for (int u = 0; u < 8; ++u)
        #pragma unroll
        for (int j = 0; j < 8; ++j) acc[u][j] = 0.f;

    #pragma unroll 4
    for (int c = 0; c < CC; ++c) {
        float4 w0 = *(float4*)&wt[c * XS_S + r0];
        float4 w1 = *(float4*)&wt[c * XS_S + r0 + 4];
        float4 x0 = *(float4*)&xs[c * XS_S + p0];
        float4 x1 = *(float4*)&xs[c * XS_S + p0 + 4];
        float wv[8] = {w0.x,w0.y,w0.z,w0.w,w1.x,w1.y,w1.z,w1.w};
        float xv[8] = {x0.x,x0.y,x0.z,x0.w,x1.x,x1.y,x1.z,x1.w};
        #pragma unroll
        for (int u = 0; u < 8; ++u)
            #pragma unroll
            for (int j = 0; j < 8; ++j)
                acc[u][j] = fmaf(wv[u], xv[j], acc[u][j]);
    }

    const float s2 = 0.17677669529663689f * 1.4426950408889634f;

    if (r0 < CC2) {
        #pragma unroll
        for (int j = 0; j < 8; ++j) {
            uint4 hv;
            hv.x = h2_u32(__floats2half2_rn(acc[0][j]*s2, acc[1][j]*s2));
            hv.y = h2_u32(__floats2half2_rn(acc[2][j]*s2, acc[3][j]*s2));
            hv.z = h2_u32(__floats2half2_rn(acc[4][j]*s2, acc[5][j]*s2));
            hv.w = h2_u32(__floats2half2_rn(acc[6][j]*s2, acc[7][j]*s2));
            *(uint4*)&g_q[((size_t)bt * PP + p0g + p0 + j) * CC2 + r0] = hv;
        }
    } else if (r0 < 2 * CC2) {
        #pragma unroll
        for (int j = 0; j < 8; ++j) {
            uint4 hv;
            hv.x = h2_u32(__floats2half2_rn(acc[0][j], acc[1][j]));
            hv.y = h2_u32(__floats2half2_rn(acc[2][j], acc[3][j]));
            hv.z = h2_u32(__floats2half2_rn(acc[4][j], acc[5][j]));
            hv.w = h2_u32(__floats2half2_rn(acc[6][j], acc[7][j]));
            *(uint4*)&g_k[((size_t)bt * PP + p0g + p0 + j) * CC2 + r0 - CC2] = hv;
        }
    } else {
        #pragma unroll
        for (int u = 0; u < 8; ++u) {
            uint4 hv;
            hv.x = h2_u32(__floats2half2_rn(acc[u][0], acc[u][1]));
            hv.y = h2_u32(__floats2half2_rn(acc[u][2], acc[u][3]));
            hv.z = h2_u32(__floats2half2_rn(acc[u][4], acc[u][5]));
            hv.w = h2_u32(__floats2half2_rn(acc[u][6], acc[u][7]));
            *(uint4*)&g_vt[((size_t)bt * VROWS + r0 - 2 * CC2 + u) * PP + p0g + p0] = hv;
        }
    }

    if (tid < 128) {
        const int row = 64 + (tid >> 4), seg = tid & 15;
        const __half2 one2 = __floats2half2_rn(1.f, 1.f);
        const u32 fill = (row == 64) ? h2_u32(one2) : 0u;
        uint4 hv = make_uint4(fill, fill, fill, fill);
        *(uint4*)&g_vt[((size_t)bt * VROWS + row) * PP + p0g + seg * 8] = hv;
    }
}

// ---------------------------------------------------------------------------
// Kernel B: flash attention via mma.sync fp16, 256 threads, grid (18,16),
// 2 CTAs/SM (16 warps). S with f16 accumulation -> h2exp2 directly.
// PV loops ordered kp-outer / nf2-inner: accumulator dependency chains are
// length-2 separated by 16 independent MMAs. LDSM batched (kb x4, vb x3)
// ahead of each MMA burst. Row sums via V ones-column.
// smem: Q @0 | K0 @10240 | K1 @20480 | V0 @30720 | V1 @50304. total 69888.
// ---------------------------------------------------------------------------
#define QK_STB  80
#define VT_STB  272
#define SMB_Q   0
#define SMB_K0  10240
#define SMB_K1  20480
#define SMB_V0  30720
#define SMB_V1  50304
#define SMB_END 69888
#define OT_S    132

__global__ void __launch_bounds__(256, 2)
flash_kernel(const float* __restrict__ x_in, float* __restrict__ out) {
    extern __shared__ char smem[];
    const u32 sb  = smem_u32(smem);
    const int tid  = threadIdx.x;
    const int w    = tid >> 5, lane = tid & 31;
    const int g    = lane >> 2, tq = lane & 3;
    const int lm   = lane >> 3, lr = lane & 7;
    const int bt   = blockIdx.y, b = bt >> 3, t = bt & 7;
    const int q0   = blockIdx.x * 128;

    const __half* gqb = &g_q[(size_t)bt * PP * CC2];
    const __half* gkb = &g_k[(size_t)bt * PP * CC2];
    const __half* gvb = &g_vt[(size_t)bt * VROWS * PP];

    // ---- initial stage: Q tile + K0 + V0 ----
    {
        #pragma unroll
        for (int j = 0; j < 2; ++j) {
            int idx = tid + j * 256;
            int row = idx >> 2, col = idx & 3;
            CP16(sb + SMB_Q  + row * QK_STB + col * 16, gqb + (size_t)(q0 + row) * CC2 + col * 8);
            CP16(sb + SMB_K0 + row * QK_STB + col * 16, gkb + (size_t)row * CC2 + col * 8);
        }
        #pragma unroll
        for (int j = 0; j < 5; ++j) {
            int idx = tid + j * 256;
            if (idx < 1152) {
                int row = idx >> 4, col = idx & 15;
                CP16(sb + SMB_V0 + row * VT_STB + col * 16, gvb + (size_t)row * PP + col * 8);
            }
        }
    }
    CP_COMMIT(); CP_WAIT0();
    __syncthreads();

    // Q A-fragments (registers, whole kernel)
    u32 aq[2][4];
    {
        const u32 qb = sb + SMB_Q + (w * 16 + (lm & 1) * 8 + lr) * QK_STB + (lm >> 1) * 16;
        LDSM4(aq[0], qb);
        LDSM4(aq[1], qb + 32);
    }

    float o[9][4];
    #pragma unroll
    for (int i = 0; i < 9; ++i)
        #pragma unroll
        for (int j = 0; j < 4; ++j) o[i][j] = 0.f;

    const u32 kldb[2] = { sb + SMB_K0 + lr * QK_STB + lm * 16,
                          sb + SMB_K1 + lr * QK_STB + lm * 16 };
    const u32 vldb[2] = { sb + SMB_V0 + lr * VT_STB + lm * 16,
                          sb + SMB_V1 + lr * VT_STB + lm * 16 };

    for (int kt = 0; kt < NTILE; ++kt) {
        const int cb = kt & 1, nb = cb ^ 1;
        const bool more = (kt + 1 < NTILE);

        // prefetch next K/V tile into the other buffer
        if (more) {
            const int k0 = (kt + 1) * 128;
            const u32 kdst = sb + (nb ? SMB_K1 : SMB_K0);
            const u32 vdst = sb + (nb ? SMB_V1 : SMB_V0);
            #pragma unroll
            for (int j = 0; j < 2; ++j) {
                int idx = tid + j * 256;
                int row = idx >> 2, col = idx & 3;
                CP16(kdst + row * QK_STB + col * 16, gkb + (size_t)(k0 + row) * CC2 + col * 8);
            }
            #pragma unroll
            for (int j = 0; j < 5; ++j) {
                int idx = tid + j * 256;
                if (idx < 1152) {
                    int row = idx >> 4, col = idx & 15;
                    CP16(vdst + row * VT_STB + col * 16, gvb + (size_t)row * PP + k0 + col * 8);
                }
            }
            CP_COMMIT();
        }

        // ---- S = Q K^T (f16 accum) fused with exp2; kb batched x4 ----
        u32 pf[16][2];
        #pragma unroll
        for (int nfg = 0; nfg < 4; ++nfg) {
            u32 kb[4][4];
            #pragma unroll
            for (int i = 0; i < 4; ++i)
                LDSM4(kb[i], kldb[cb] + (nfg * 4 + i) * 8 * QK_STB);
            #pragma unroll
            for (int i = 0; i < 4; ++i) {
                const int nf = nfg * 4 + i;
                u32 d[2] = {0u, 0u};
                MMAF16H(d, aq[0][0], aq[0][1], aq[0][2], aq[0][3], kb[i][0], kb[i][1]);
                MMAF16H(d, aq[1][0], aq[1][1], aq[1][2], aq[1][3], kb[i][2], kb[i][3]);
                pf[nf][0] = h2_u32(h2exp2(*(__half2*)&d[0]));
                pf[nf][1] = h2_u32(h2exp2(*(__half2*)&d[1]));
            }
        }

        // ---- O += P V : kp outer, nf2 inner (chains len 2, 16 MMAs apart);
        //      vb batched x3 ----
        #pragma unroll
        for (int kp = 0; kp < 4; ++kp) {
            #pragma unroll
            for (int ng = 0; ng < 3; ++ng) {
                u32 vb[3][4];
                #pragma unroll
                for (int i = 0; i < 3; ++i)
                    LDSM4(vb[i], vldb[cb] + (ng * 3 + i) * 8 * VT_STB + kp * 64);
                #pragma unroll
                for (int i = 0; i < 3; ++i) {
                    const int nf2 = ng * 3 + i;
                    MMAF16(o[nf2], pf[4*kp][0], pf[4*kp][1], pf[4*kp+1][0], pf[4*kp+1][1], vb[i][0], vb[i][1]);
                    MMAF16(o[nf2], pf[4*kp+2][0], pf[4*kp+2][1], pf[4*kp+3][0], pf[4*kp+3][1], vb[i][2], vb[i][3]);
                }
            }
        }

        CP_WAIT0();
        __syncthreads();
    }

    // ---- row sums from ones-column (col 64 lives in tq==0 lanes) ----
    const int qlead = lane & 28;
    const float inv_lo = 1.f / __shfl_sync(0xffffffffu, o[8][0], qlead);
    const float inv_hi = 1.f / __shfl_sync(0xffffffffu, o[8][2], qlead);

    float* ot = (float*)smem;
    const int prow = w * 16 + g;
    #pragma unroll
    for (int nf2 = 0; nf2 < 8; ++nf2) {
        int oc = nf2 * 8 + 2 * tq;
        ot[(oc    ) * OT_S + prow    ] = o[nf2][0] * inv_lo;
        ot[(oc + 1) * OT_S + prow    ] = o[nf2][1] * inv_lo;
        ot[(oc    ) * OT_S + prow + 8] = o[nf2][2] * inv_hi;
        ot[(oc + 1) * OT_S + prow + 8] = o[nf2][3] * inv_hi;
    }
    __syncthreads();

    // out[b, o, t, q0 + p] = O^T + residual (coalesced float4)
    {
        const int oc = tid >> 2, qt = tid & 3;
        const size_t gb = ((size_t)(b * CC + oc) * TT + t) * PP + q0 + qt * 32;
        const float* src = &ot[oc * OT_S + qt * 32];
        #pragma unroll
        for (int j = 0; j < 8; ++j) {
            float4 v = *(const float4*)&src[4 * j];
            float4 x = *(const float4*)&x_in[gb + 4 * j];
            v.x += x.x; v.y += x.y; v.z += x.z; v.w += x.w;
            *(float4*)&out[gb + 4 * j] = v;
        }
    }
}

// ---------------------------------------------------------------------------

extern "C" void kernel_launch(void* const* d_in, const int* in_sizes, int n_in,
                              void* d_out, int out_size) {
    const float* x_in = (const float*)d_in[0];
    const float* thw  = (const float*)d_in[1];
    const float* phw  = (const float*)d_in[2];
    const float* ow   = (const float*)d_in[3];
    float* out = (float*)d_out;

    const int prep_smem  = 2 * CC * XS_S * 4;  // 67584 B
    const int flash_smem = SMB_END;            // 69888 B

    cudaFuncSetAttribute(prep_kernel,  cudaFuncAttributeMaxDynamicSharedMemorySize, prep_smem);
    cudaFuncSetAttribute(flash_kernel, cudaFuncAttributeMaxDynamicSharedMemorySize, flash_smem);

    prep_kernel<<<dim3(NBT, PP / 128), 256, prep_smem>>>(x_in, thw, phw, ow);
    flash_kernel<<<dim3(PP / 128, NBT), 256, flash_smem>>>(x_in, out);
}

// round 13
// speedup vs baseline: 1.4618x; 1.0928x over previous
#include <cuda_runtime.h>
#include <cuda_fp16.h>
#include <cstdint>

#define CC    64
#define CC2   32
#define TT    8
#define PP    2304
#define NBT   16
#define NTILE 18
#define VROWS 64

typedef unsigned int u32;

__device__ __half g_q [NBT * PP * CC2];      // theta * scale * log2e, [bt][p][32]
__device__ __half g_k [NBT * PP * CC2];      // phi,                  [bt][p][32]
__device__ __half g_vt[NBT * VROWS * PP];    // (out_w @ x)^T, [bt][o][p]

__device__ __forceinline__ u32 smem_u32(const void* p){
    u32 a; asm("{ .reg .u64 t; cvta.to.shared.u64 t, %1; cvt.u32.u64 %0, t; }":"=r"(a):"l"(p)); return a;
}

#define LDSM4(r, a) \
    asm volatile("ldmatrix.sync.aligned.m8n8.x4.shared.b16 {%0,%1,%2,%3}, [%4];" \
        : "=r"((r)[0]),"=r"((r)[1]),"=r"((r)[2]),"=r"((r)[3]) : "r"(a))

#define MMAF16(d, a0, a1, a2, a3, b0, b1) \
    asm volatile("mma.sync.aligned.m16n8k16.row.col.f32.f16.f16.f32 " \
        "{%0,%1,%2,%3}, {%4,%5,%6,%7}, {%8,%9}, {%0,%1,%2,%3};" \
        : "+f"((d)[0]),"+f"((d)[1]),"+f"((d)[2]),"+f"((d)[3]) \
        : "r"(a0),"r"(a1),"r"(a2),"r"(a3), "r"(b0),"r"(b1))

// f16-accumulate variant: D/C are 2x b32 (f16x2); layout == A-fragment layout.
#define MMAF16H(d, a0, a1, a2, a3, b0, b1) \
    asm volatile("mma.sync.aligned.m16n8k16.row.col.f16.f16.f16.f16 " \
        "{%0,%1}, {%2,%3,%4,%5}, {%6,%7}, {%0,%1};" \
        : "+r"((d)[0]),"+r"((d)[1]) \
        : "r"(a0),"r"(a1),"r"(a2),"r"(a3), "r"(b0),"r"(b1))

#define CP16(dst, src) \
    asm volatile("cp.async.cg.shared.global [%0], [%1], 16;" :: "r"(dst), "l"(src))
#define CP_COMMIT() asm volatile("cp.async.commit_group;" ::: "memory")
#define CP_WAIT0()  asm volatile("cp.async.wait_group 0;" ::: "memory")

__device__ __forceinline__ u32 h2_u32(__half2 h){ return *(u32*)&h; }
__device__ __forceinline__ __half2 u32_h2(u32 v){ return *(__half2*)&v; }

// ---------------------------------------------------------------------------
// Kernel A: per-(b,t) projections, 8x8 outer-product register tiles (FFMA
// roofline). out_w folded into V; V transposed [o][p]. grid (16,18), 256 thr.
// ---------------------------------------------------------------------------
#define XS_S 132
__global__ void __launch_bounds__(256)
prep_kernel(const float* __restrict__ x_in,
            const float* __restrict__ thw,
            const float* __restrict__ phw,
            const float* __restrict__ ow) {
    extern __shared__ float sm[];
    float* xs = sm;               // [64][132]
    float* wt = sm + CC * XS_S;   // [64][132]

    const int bt = blockIdx.x, b = bt >> 3, t = bt & 7;
    const int p0g = blockIdx.y * 128;
    const int tid = threadIdx.x;

    for (int i = tid; i < CC * 128; i += 256) {
        int c = i >> 7, pl = i & 127;
        xs[c * XS_S + pl] = x_in[((b * CC + c) * TT + t) * PP + p0g + pl];
    }
    for (int i = tid; i < CC2 * CC; i += 256) {
        int o = i >> 6, c = i & 63;
        wt[c * XS_S + o]      = thw[t * CC2 * CC + i];
        wt[c * XS_S + 32 + o] = phw[t * CC2 * CC + i];
    }
    for (int i = tid; i < CC * CC; i += 256) {
        int o = i >> 6, c = i & 63;
        wt[c * XS_S + 64 + o] = ow[i];
    }
    __syncthreads();

    const int r0 = (tid >> 4) << 3;
    const int p0 = (tid & 15) << 3;

    float acc[8][8];
    #pragma unroll
    for (int u = 0; u < 8; ++u)
        #pragma unroll
        for (int j = 0; j < 8; ++j) acc[u][j] = 0.f;

    #pragma unroll 4
    for (int c = 0; c < CC; ++c) {
        float4 w0 = *(float4*)&wt[c * XS_S + r0];
        float4 w1 = *(float4*)&wt[c * XS_S + r0 + 4];
        float4 x0 = *(float4*)&xs[c * XS_S + p0];
        float4 x1 = *(float4*)&xs[c * XS_S + p0 + 4];
        float wv[8] = {w0.x,w0.y,w0.z,w0.w,w1.x,w1.y,w1.z,w1.w};
        float xv[8] = {x0.x,x0.y,x0.z,x0.w,x1.x,x1.y,x1.z,x1.w};
        #pragma unroll
        for (int u = 0; u < 8; ++u)
            #pragma unroll
            for (int j = 0; j < 8; ++j)
                acc[u][j] = fmaf(wv[u], xv[j], acc[u][j]);
    }

    const float s2 = 0.17677669529663689f * 1.4426950408889634f;

    if (r0 < CC2) {
        #pragma unroll
        for (int j = 0; j < 8; ++j) {
            uint4 hv;
            hv.x = h2_u32(__floats2half2_rn(acc[0][j]*s2, acc[1][j]*s2));
            hv.y = h2_u32(__floats2half2_rn(acc[2][j]*s2, acc[3][j]*s2));
            hv.z = h2_u32(__floats2half2_rn(acc[4][j]*s2, acc[5][j]*s2));
            hv.w = h2_u32(__floats2half2_rn(acc[6][j]*s2, acc[7][j]*s2));
            *(uint4*)&g_q[((size_t)bt * PP + p0g + p0 + j) * CC2 + r0] = hv;
        }
    } else if (r0 < 2 * CC2) {
        #pragma unroll
        for (int j = 0; j < 8; ++j) {
            uint4 hv;
            hv.x = h2_u32(__floats2half2_rn(acc[0][j], acc[1][j]));
            hv.y = h2_u32(__floats2half2_rn(acc[2][j], acc[3][j]));
            hv.z = h2_u32(__floats2half2_rn(acc[4][j], acc[5][j]));
            hv.w = h2_u32(__floats2half2_rn(acc[6][j], acc[7][j]));
            *(uint4*)&g_k[((size_t)bt * PP + p0g + p0 + j) * CC2 + r0 - CC2] = hv;
        }
    } else {
        #pragma unroll
        for (int u = 0; u < 8; ++u) {
            uint4 hv;
            hv.x = h2_u32(__floats2half2_rn(acc[u][0], acc[u][1]));
            hv.y = h2_u32(__floats2half2_rn(acc[u][2], acc[u][3]));
            hv.z = h2_u32(__floats2half2_rn(acc[u][4], acc[u][5]));
            hv.w = h2_u32(__floats2half2_rn(acc[u][6], acc[u][7]));
            *(uint4*)&g_vt[((size_t)bt * VROWS + r0 - 2 * CC2 + u) * PP + p0g + p0] = hv;
        }
    }
}

// ---------------------------------------------------------------------------
// Kernel B: flash attention, cross-tile software pipeline: body kt runs
// PV(kt) interleaved with S(kt+1) at kp granularity, pf overwritten in place.
// K prefetched 2 tiles ahead, V 1 ahead. Row sums via HADD2 (fma pipe).
// 256 threads, grid (18,16), 2 CTAs/SM.
// smem: Q @0 | K0 @10240 | K1 @20480 | V0 @30720 | V1 @48128 (64x272B) = 65536.
// ---------------------------------------------------------------------------
#define QK_STB  80
#define VT_STB  272
#define SMB_Q   0
#define SMB_K0  10240
#define SMB_K1  20480
#define SMB_V0  30720
#define SMB_V1  48128
#define SMB_END 65536
#define OT_S    132

__global__ void __launch_bounds__(256, 2)
flash_kernel(const float* __restrict__ x_in, float* __restrict__ out) {
    extern __shared__ char smem[];
    const u32 sb  = smem_u32(smem);
    const int tid  = threadIdx.x;
    const int w    = tid >> 5, lane = tid & 31;
    const int g    = lane >> 2, tq = lane & 3;
    const int lm   = lane >> 3, lr = lane & 7;
    const int bt   = blockIdx.y, b = bt >> 3, t = bt & 7;
    const int q0   = blockIdx.x * 128;

    const __half* gqb = &g_q[(size_t)bt * PP * CC2];
    const __half* gkb = &g_k[(size_t)bt * PP * CC2];
    const __half* gvb = &g_vt[(size_t)bt * VROWS * PP];

    // ---- prologue stage: Q + K0 + V0 + K1 ----
    {
        #pragma unroll
        for (int j = 0; j < 2; ++j) {
            int idx = tid + j * 256;
            int row = idx >> 2, col = idx & 3;
            CP16(sb + SMB_Q  + row * QK_STB + col * 16, gqb + (size_t)(q0 + row) * CC2 + col * 8);
            CP16(sb + SMB_K0 + row * QK_STB + col * 16, gkb + (size_t)row * CC2 + col * 8);
            CP16(sb + SMB_K1 + row * QK_STB + col * 16, gkb + (size_t)(128 + row) * CC2 + col * 8);
        }
        #pragma unroll
        for (int j = 0; j < 4; ++j) {
            int idx = tid + j * 256;
            int row = idx >> 4, col = idx & 15;
            CP16(sb + SMB_V0 + row * VT_STB + col * 16, gvb + (size_t)row * PP + col * 8);
        }
    }
    CP_COMMIT(); CP_WAIT0();
    __syncthreads();

    // Q A-fragments (registers, whole kernel)
    u32 aq[2][4];
    {
        const u32 qb = sb + SMB_Q + (w * 16 + (lm & 1) * 8 + lr) * QK_STB + (lm >> 1) * 16;
        LDSM4(aq[0], qb);
        LDSM4(aq[1], qb + 32);
    }

    const u32 kldb[2] = { sb + SMB_K0 + lr * QK_STB + lm * 16,
                          sb + SMB_K1 + lr * QK_STB + lm * 16 };
    const u32 vldb[2] = { sb + SMB_V0 + lr * VT_STB + lm * 16,
                          sb + SMB_V1 + lr * VT_STB + lm * 16 };

    // ---- S(0) -> pf ----
    u32 pf[16][2];
    #pragma unroll
    for (int nfg = 0; nfg < 4; ++nfg) {
        u32 kb[4][4];
        #pragma unroll
        for (int i = 0; i < 4; ++i)
            LDSM4(kb[i], kldb[0] + (nfg * 4 + i) * 8 * QK_STB);
        #pragma unroll
        for (int i = 0; i < 4; ++i) {
            u32 d[2] = {0u, 0u};
            MMAF16H(d, aq[0][0], aq[0][1], aq[0][2], aq[0][3], kb[i][0], kb[i][1]);
            MMAF16H(d, aq[1][0], aq[1][1], aq[1][2], aq[1][3], kb[i][2], kb[i][3]);
            pf[nfg * 4 + i][0] = h2_u32(h2exp2(u32_h2(d[0])));
            pf[nfg * 4 + i][1] = h2_u32(h2exp2(u32_h2(d[1])));
        }
    }
    __syncthreads();   // Kb0 must be fully read before body-0 prefetches K2 into it

    float o[8][4];
    #pragma unroll
    for (int i = 0; i < 8; ++i)
        #pragma unroll
        for (int j = 0; j < 4; ++j) o[i][j] = 0.f;
    float lsum_lo = 0.f, lsum_hi = 0.f;

    for (int kt = 0; kt < NTILE; ++kt) {
        const int cb = kt & 1;
        const bool more = (kt + 1 < NTILE);

        // prefetch V(kt+1) and K(kt+2)
        if (more) {
            const int kv = (kt + 1) * 128;
            const u32 vdst = sb + (((kt + 1) & 1) ? SMB_V1 : SMB_V0);
            #pragma unroll
            for (int j = 0; j < 4; ++j) {
                int idx = tid + j * 256;
                int row = idx >> 4, col = idx & 15;
                CP16(vdst + row * VT_STB + col * 16, gvb + (size_t)row * PP + kv + col * 8);
            }
            if (kt + 2 < NTILE) {
                const int kk = (kt + 2) * 128;
                const u32 kdst = sb + ((kt & 1) ? SMB_K1 : SMB_K0);
                #pragma unroll
                for (int j = 0; j < 2; ++j) {
                    int idx = tid + j * 256;
                    int row = idx >> 2, col = idx & 3;
                    CP16(kdst + row * QK_STB + col * 16, gkb + (size_t)(kk + row) * CC2 + col * 8);
                }
            }
        }
        CP_COMMIT();

        const u32 vaddr = vldb[cb];
        const u32 kaddr = kldb[(kt + 1) & 1];

        __half2 hsum_lo = __floats2half2_rn(0.f, 0.f);
        __half2 hsum_hi = __floats2half2_rn(0.f, 0.f);

        // ---- interleaved PV(kt) + S(kt+1), per 32-key kp block ----
        #pragma unroll
        for (int kp = 0; kp < 4; ++kp) {
            u32 kb[2][4], kb2[2][4], d[4][2];
            if (more) {
                LDSM4(kb[0], kaddr + (4 * kp    ) * 8 * QK_STB);
                LDSM4(kb[1], kaddr + (4 * kp + 1) * 8 * QK_STB);
            }
            {
                u32 vb[2][4];
                LDSM4(vb[0], vaddr + 0 * 8 * VT_STB + kp * 64);
                LDSM4(vb[1], vaddr + 1 * 8 * VT_STB + kp * 64);
                MMAF16(o[0], pf[4*kp][0], pf[4*kp][1], pf[4*kp+1][0], pf[4*kp+1][1], vb[0][0], vb[0][1]);
                MMAF16(o[0], pf[4*kp+2][0], pf[4*kp+2][1], pf[4*kp+3][0], pf[4*kp+3][1], vb[0][2], vb[0][3]);
                MMAF16(o[1], pf[4*kp][0], pf[4*kp][1], pf[4*kp+1][0], pf[4*kp+1][1], vb[1][0], vb[1][1]);
                MMAF16(o[1], pf[4*kp+2][0], pf[4*kp+2][1], pf[4*kp+3][0], pf[4*kp+3][1], vb[1][2], vb[1][3]);
            }
            if (more) {
                d[0][0] = 0u; d[0][1] = 0u;
                MMAF16H(d[0], aq[0][0], aq[0][1], aq[0][2], aq[0][3], kb[0][0], kb[0][1]);
                MMAF16H(d[0], aq[1][0], aq[1][1], aq[1][2], aq[1][3], kb[0][2], kb[0][3]);
                d[1][0] = 0u; d[1][1] = 0u;
                MMAF16H(d[1], aq[0][0], aq[0][1], aq[0][2], aq[0][3], kb[1][0], kb[1][1]);
                MMAF16H(d[1], aq[1][0], aq[1][1], aq[1][2], aq[1][3], kb[1][2], kb[1][3]);
                LDSM4(kb2[0], kaddr + (4 * kp + 2) * 8 * QK_STB);
                LDSM4(kb2[1], kaddr + (4 * kp + 3) * 8 * QK_STB);
            }
            {
                u32 vb[2][4];
                LDSM4(vb[0], vaddr + 2 * 8 * VT_STB + kp * 64);
                LDSM4(vb[1], vaddr + 3 * 8 * VT_STB + kp * 64);
                MMAF16(o[2], pf[4*kp][0], pf[4*kp][1], pf[4*kp+1][0], pf[4*kp+1][1], vb[0][0], vb[0][1]);
                MMAF16(o[2], pf[4*kp+2][0], pf[4*kp+2][1], pf[4*kp+3][0], pf[4*kp+3][1], vb[0][2], vb[0][3]);
                MMAF16(o[3], pf[4*kp][0], pf[4*kp][1], pf[4*kp+1][0], pf[4*kp+1][1], vb[1][0], vb[1][1]);
                MMAF16(o[3], pf[4*kp+2][0], pf[4*kp+2][1], pf[4*kp+3][0], pf[4*kp+3][1], vb[1][2], vb[1][3]);
            }
            if (more) {
                d[2][0] = 0u; d[2][1] = 0u;
                MMAF16H(d[2], aq[0][0], aq[0][1], aq[0][2], aq[0][3], kb2[0][0], kb2[0][1]);
                MMAF16H(d[2], aq[1][0], aq[1][1], aq[1][2], aq[1][3], kb2[0][2], kb2[0][3]);
                d[3][0] = 0u; d[3][1] = 0u;
                MMAF16H(d[3], aq[0][0], aq[0][1], aq[0][2], aq[0][3], kb2[1][0], kb2[1][1]);
                MMAF16H(d[3], aq[1][0], aq[1][1], aq[1][2], aq[1][3], kb2[1][2], kb2[1][3]);
            }
            {
                u32 vb[2][4];
                LDSM4(vb[0], vaddr + 4 * 8 * VT_STB + kp * 64);
                LDSM4(vb[1], vaddr + 5 * 8 * VT_STB + kp * 64);
                MMAF16(o[4], pf[4*kp][0], pf[4*kp][1], pf[4*kp+1][0], pf[4*kp+1][1], vb[0][0], vb[0][1]);
                MMAF16(o[4], pf[4*kp+2][0], pf[4*kp+2][1], pf[4*kp+3][0], pf[4*kp+3][1], vb[0][2], vb[0][3]);
                MMAF16(o[5], pf[4*kp][0], pf[4*kp][1], pf[4*kp+1][0], pf[4*kp+1][1], vb[1][0], vb[1][1]);
                MMAF16(o[5], pf[4*kp+2][0], pf[4*kp+2][1], pf[4*kp+3][0], pf[4*kp+3][1], vb[1][2], vb[1][3]);
            }
            // row-sum contributions of this kp's P (before overwrite)
            hsum_lo = __hadd2(__hadd2(hsum_lo, u32_h2(pf[4*kp][0])),
                              __hadd2(u32_h2(pf[4*kp+1][0]), u32_h2(pf[4*kp+2][0])));
            hsum_lo = __hadd2(hsum_lo, u32_h2(pf[4*kp+3][0]));
            hsum_hi = __hadd2(__hadd2(hsum_hi, u32_h2(pf[4*kp][1])),
                              __hadd2(u32_h2(pf[4*kp+1][1]), u32_h2(pf[4*kp+2][1])));
            hsum_hi = __hadd2(hsum_hi, u32_h2(pf[4*kp+3][1]));
            {
                u32 vb[2][4];
                LDSM4(vb[0], vaddr + 6 * 8 * VT_STB + kp * 64);
                LDSM4(vb[1], vaddr + 7 * 8 * VT_STB + kp * 64);
                MMAF16(o[6], pf[4*kp][0], pf[4*kp][1], pf[4*kp+1][0], pf[4*kp+1][1], vb[0][0], vb[0][1]);
                MMAF16(o[6], pf[4*kp+2][0], pf[4*kp+2][1], pf[4*kp+3][0], pf[4*kp+3][1], vb[0][2], vb[0][3]);
                MMAF16(o[7], pf[4*kp][0], pf[4*kp][1], pf[4*kp+1][0], pf[4*kp+1][1], vb[1][0], vb[1][1]);
                MMAF16(o[7], pf[4*kp+2][0], pf[4*kp+2][1], pf[4*kp+3][0], pf[4*kp+3][1], vb[1][2], vb[1][3]);
            }
            if (more) {
                pf[4*kp    ][0] = h2_u32(h2exp2(u32_h2(d[0][0])));
                pf[4*kp    ][1] = h2_u32(h2exp2(u32_h2(d[0][1])));
                pf[4*kp + 1][0] = h2_u32(h2exp2(u32_h2(d[1][0])));
                pf[4*kp + 1][1] = h2_u32(h2exp2(u32_h2(d[1][1])));
                pf[4*kp + 2][0] = h2_u32(h2exp2(u32_h2(d[2][0])));
                pf[4*kp + 2][1] = h2_u32(h2exp2(u32_h2(d[2][1])));
                pf[4*kp + 3][0] = h2_u32(h2exp2(u32_h2(d[3][0])));
                pf[4*kp + 3][1] = h2_u32(h2exp2(u32_h2(d[3][1])));
            }
        }

        // fold tile sums into f32
        {
            float2 fl = __half22float2(hsum_lo);
            float2 fh = __half22float2(hsum_hi);
            lsum_lo += fl.x + fl.y;
            lsum_hi += fh.x + fh.y;
        }

        CP_WAIT0();
        __syncthreads();
    }

    // ---- quad-reduce row sums, normalize, transpose via smem ----
    lsum_lo += __shfl_xor_sync(0xffffffffu, lsum_lo, 1);
    lsum_lo += __shfl_xor_sync(0xffffffffu, lsum_lo, 2);
    lsum_hi += __shfl_xor_sync(0xffffffffu, lsum_hi, 1);
    lsum_hi += __shfl_xor_sync(0xffffffffu, lsum_hi, 2);
    const float inv_lo = 1.f / lsum_lo, inv_hi = 1.f / lsum_hi;

    float* ot = (float*)smem;
    const int prow = w * 16 + g;
    #pragma unroll
    for (int nf2 = 0; nf2 < 8; ++nf2) {
        int oc = nf2 * 8 + 2 * tq;
        ot[(oc    ) * OT_S + prow    ] = o[nf2][0] * inv_lo;
        ot[(oc + 1) * OT_S + prow    ] = o[nf2][1] * inv_lo;
        ot[(oc    ) * OT_S + prow + 8] = o[nf2][2] * inv_hi;
        ot[(oc + 1) * OT_S + prow + 8] = o[nf2][3] * inv_hi;
    }
    __syncthreads();

    // out[b, o, t, q0 + p] = O^T + residual (coalesced float4)
    {
        const int oc = tid >> 2, qt = tid & 3;
        const size_t gb = ((size_t)(b * CC + oc) * TT + t) * PP + q0 + qt * 32;
        const float* src = &ot[oc * OT_S + qt * 32];
        #pragma unroll
        for (int j = 0; j < 8; ++j) {
            float4 v = *(const float4*)&src[4 * j];
            float4 x = *(const float4*)&x_in[gb + 4 * j];
            v.x += x.x; v.y += x.y; v.z += x.z; v.w += x.w;
            *(float4*)&out[gb + 4 * j] = v;
        }
    }
}

// ---------------------------------------------------------------------------

extern "C" void kernel_launch(void* const* d_in, const int* in_sizes, int n_in,
                              void* d_out, int out_size) {
    const float* x_in = (const float*)d_in[0];
    const float* thw  = (const float*)d_in[1];
    const float* phw  = (const float*)d_in[2];
    const float* ow   = (const float*)d_in[3];
    float* out = (float*)d_out;

    const int prep_smem  = 2 * CC * XS_S * 4;  // 67584 B
    const int flash_smem = SMB_END;            // 65536 B

    cudaFuncSetAttribute(prep_kernel,  cudaFuncAttributeMaxDynamicSharedMemorySize, prep_smem);
    cudaFuncSetAttribute(flash_kernel, cudaFuncAttributeMaxDynamicSharedMemorySize, flash_smem);

    prep_kernel<<<dim3(NBT, PP / 128), 256, prep_smem>>>(x_in, thw, phw, ow);
    flash_kernel<<<dim3(PP / 128, NBT), 256, flash_smem>>>(x_in, out);
}

// round 15
// speedup vs baseline: 1.5409x; 1.0541x over previous
#include <cuda_runtime.h>
#include <cuda_fp16.h>
#include <cstdint>

#define CC    64
#define CC2   32
#define TT    8
#define PP    2304
#define NBT   16
#define NTILE 18
#define VROWS 64

typedef unsigned int u32;

__device__ __half g_q [NBT * PP * CC2];      // theta * scale * log2e, [bt][p][32]
__device__ __half g_k [NBT * PP * CC2];      // phi,                  [bt][p][32]
__device__ __half g_vt[NBT * VROWS * PP];    // (out_w @ x)^T, [bt][o][p]

__device__ __forceinline__ u32 smem_u32(const void* p){
    u32 a; asm("{ .reg .u64 t; cvta.to.shared.u64 t, %1; cvt.u32.u64 %0, t; }":"=r"(a):"l"(p)); return a;
}

#define LDSM4(r, a) \
    asm volatile("ldmatrix.sync.aligned.m8n8.x4.shared.b16 {%0,%1,%2,%3}, [%4];" \
        : "=r"((r)[0]),"=r"((r)[1]),"=r"((r)[2]),"=r"((r)[3]) : "r"(a))

#define MMAF16(d, a0, a1, a2, a3, b0, b1) \
    asm volatile("mma.sync.aligned.m16n8k16.row.col.f32.f16.f16.f32 " \
        "{%0,%1,%2,%3}, {%4,%5,%6,%7}, {%8,%9}, {%0,%1,%2,%3};" \
        : "+f"((d)[0]),"+f"((d)[1]),"+f"((d)[2]),"+f"((d)[3]) \
        : "r"(a0),"r"(a1),"r"(a2),"r"(a3), "r"(b0),"r"(b1))

// f16-accumulate variant: D/C are 2x b32 (f16x2); layout == A-fragment layout.
#define MMAF16H(d, a0, a1, a2, a3, b0, b1) \
    asm volatile("mma.sync.aligned.m16n8k16.row.col.f16.f16.f16.f16 " \
        "{%0,%1}, {%2,%3,%4,%5}, {%6,%7}, {%0,%1};" \
        : "+r"((d)[0]),"+r"((d)[1]) \
        : "r"(a0),"r"(a1),"r"(a2),"r"(a3), "r"(b0),"r"(b1))

#define CP16(dst, src) \
    asm volatile("cp.async.cg.shared.global [%0], [%1], 16;" :: "r"(dst), "l"(src))
#define CP_COMMIT() asm volatile("cp.async.commit_group;" ::: "memory")
#define CP_WAIT0()  asm volatile("cp.async.wait_group 0;" ::: "memory")

__device__ __forceinline__ u32 h2_u32(__half2 h){ return *(u32*)&h; }
__device__ __forceinline__ __half2 u32_h2(u32 v){ return *(__half2*)&v; }

// ---------------------------------------------------------------------------
// Kernel A: per-(b,t) projections, 8x8 outer-product register tiles (FFMA
// roofline). out_w folded into V; V transposed [o][p]. grid (16,18), 256 thr.
// ---------------------------------------------------------------------------
#define XS_S 132
__global__ void __launch_bounds__(256)
prep_kernel(const float* __restrict__ x_in,
            const float* __restrict__ thw,
            const float* __restrict__ phw,
            const float* __restrict__ ow) {
    extern __shared__ float sm[];
    float* xs = sm;               // [64][132]
    float* wt = sm + CC * XS_S;   // [64][132]

    const int bt = blockIdx.x, b = bt >> 3, t = bt & 7;
    const int p0g = blockIdx.y * 128;
    const int tid = threadIdx.x;

    for (int i = tid; i < CC * 128; i += 256) {
        int c = i >> 7, pl = i & 127;
        xs[c * XS_S + pl] = x_in[((b * CC + c) * TT + t) * PP + p0g + pl];
    }
    for (int i = tid; i < CC2 * CC; i += 256) {
        int o = i >> 6, c = i & 63;
        wt[c * XS_S + o]      = thw[t * CC2 * CC + i];
        wt[c * XS_S + 32 + o] = phw[t * CC2 * CC + i];
    }
    for (int i = tid; i < CC * CC; i += 256) {
        int o = i >> 6, c = i & 63;
        wt[c * XS_S + 64 + o] = ow[i];
    }
    __syncthreads();

    const int r0 = (tid >> 4) << 3;
    const int p0 = (tid & 15) << 3;

    float acc[8][8];
    #pragma unroll
    for (int u = 0; u < 8; ++u)
        #pragma unroll
        for (int j = 0; j < 8; ++j) acc[u][j] = 0.f;

    #pragma unroll 4
    for (int c = 0; c < CC; ++c) {
        float4 w0 = *(float4*)&wt[c * XS_S + r0];
        float4 w1 = *(float4*)&wt[c * XS_S + r0 + 4];
        float4 x0 = *(float4*)&xs[c * XS_S + p0];
        float4 x1 = *(float4*)&xs[c * XS_S + p0 + 4];
        float wv[8] = {w0.x,w0.y,w0.z,w0.w,w1.x,w1.y,w1.z,w1.w};
        float xv[8] = {x0.x,x0.y,x0.z,x0.w,x1.x,x1.y,x1.z,x1.w};
        #pragma unroll
        for (int u = 0; u < 8; ++u)
            #pragma unroll
            for (int j = 0; j < 8; ++j)
                acc[u][j] = fmaf(wv[u], xv[j], acc[u][j]);
    }

    const float s2 = 0.17677669529663689f * 1.4426950408889634f;

    if (r0 < CC2) {
        #pragma unroll
        for (int j = 0; j < 8; ++j) {
            uint4 hv;
            hv.x = h2_u32(__floats2half2_rn(acc[0][j]*s2, acc[1][j]*s2));
            hv.y = h2_u32(__floats2half2_rn(acc[2][j]*s2, acc[3][j]*s2));
            hv.z = h2_u32(__floats2half2_rn(acc[4][j]*s2, acc[5][j]*s2));
            hv.w = h2_u32(__floats2half2_rn(acc[6][j]*s2, acc[7][j]*s2));
            *(uint4*)&g_q[((size_t)bt * PP + p0g + p0 + j) * CC2 + r0] = hv;
        }
    } else if (r0 < 2 * CC2) {
        #pragma unroll
        for (int j = 0; j < 8; ++j) {
            uint4 hv;
            hv.x = h2_u32(__floats2half2_rn(acc[0][j], acc[1][j]));
            hv.y = h2_u32(__floats2half2_rn(acc[2][j], acc[3][j]));
            hv.z = h2_u32(__floats2half2_rn(acc[4][j], acc[5][j]));
            hv.w = h2_u32(__floats2half2_rn(acc[6][j], acc[7][j]));
            *(uint4*)&g_k[((size_t)bt * PP + p0g + p0 + j) * CC2 + r0 - CC2] = hv;
        }
    } else {
        #pragma unroll
        for (int u = 0; u < 8; ++u) {
            uint4 hv;
            hv.x = h2_u32(__floats2half2_rn(acc[u][0], acc[u][1]));
            hv.y = h2_u32(__floats2half2_rn(acc[u][2], acc[u][3]));
            hv.z = h2_u32(__floats2half2_rn(acc[u][4], acc[u][5]));
            hv.w = h2_u32(__floats2half2_rn(acc[u][6], acc[u][7]));
            *(uint4*)&g_vt[((size_t)bt * VROWS + r0 - 2 * CC2 + u) * PP + p0g + p0] = hv;
        }
    }
}

// ---------------------------------------------------------------------------
// Kernel B: flash attention, 128 threads (4 warps), 32 q-rows/warp in 2 row
// groups -> every K/V fragment LDSM feeds 2x MMAs (per-SM smem traffic
// halved vs 16-row warps). grid (18,16)=288 -> ~2 CTAs/SM. S (f16 accum)
// and PV interleaved per 32-key kp block; row sums via HADD2 on fma pipe.
// smem: Q @0 (128x80) | K0 @10240 | K1 @20480 | V0 @30720 | V1 @48128 = 65536.
// Epilogue reuses smem as O^T [64][132] f32.
// ---------------------------------------------------------------------------
#define QK_STB  80
#define VT_STB  272
#define SMB_Q   0
#define SMB_K0  10240
#define SMB_K1  20480
#define SMB_V0  30720
#define SMB_V1  48128
#define SMB_END 65536
#define OT_S    132

__global__ void __launch_bounds__(128, 3)
flash_kernel(const float* __restrict__ x_in, float* __restrict__ out) {
    extern __shared__ char smem[];
    const u32 sb  = smem_u32(smem);
    const int tid  = threadIdx.x;
    const int w    = tid >> 5, lane = tid & 31;
    const int g    = lane >> 2, tq = lane & 3;
    const int lm   = lane >> 3, lr = lane & 7;
    const int bt   = blockIdx.y, b = bt >> 3, t = bt & 7;
    const int q0   = blockIdx.x * 128;

    const __half* gqb = &g_q[(size_t)bt * PP * CC2];
    const __half* gkb = &g_k[(size_t)bt * PP * CC2];
    const __half* gvb = &g_vt[(size_t)bt * VROWS * PP];

    // ---- prologue stage: Q + K0 + V0 ----
    {
        #pragma unroll
        for (int j = 0; j < 4; ++j) {
            int idx = tid + j * 128;
            int row = idx >> 2, col = idx & 3;
            CP16(sb + SMB_Q  + row * QK_STB + col * 16, gqb + (size_t)(q0 + row) * CC2 + col * 8);
            CP16(sb + SMB_K0 + row * QK_STB + col * 16, gkb + (size_t)row * CC2 + col * 8);
        }
        #pragma unroll
        for (int j = 0; j < 8; ++j) {
            int idx = tid + j * 128;
            int row = idx >> 4, col = idx & 15;
            CP16(sb + SMB_V0 + row * VT_STB + col * 16, gvb + (size_t)row * PP + col * 8);
        }
    }
    CP_COMMIT(); CP_WAIT0();
    __syncthreads();

    // Q A-fragments: 2 row groups (rows w*32 and w*32+16)
    u32 aq[2][2][4];
    #pragma unroll
    for (int rg = 0; rg < 2; ++rg) {
        const u32 qb = sb + SMB_Q + (w * 32 + rg * 16 + (lm & 1) * 8 + lr) * QK_STB + (lm >> 1) * 16;
        LDSM4(aq[rg][0], qb);
        LDSM4(aq[rg][1], qb + 32);
    }

    float o[2][8][4];
    #pragma unroll
    for (int rg = 0; rg < 2; ++rg)
        #pragma unroll
        for (int i = 0; i < 8; ++i)
            #pragma unroll
            for (int j = 0; j < 4; ++j) o[rg][i][j] = 0.f;
    float lsum[2][2];
    lsum[0][0] = lsum[0][1] = lsum[1][0] = lsum[1][1] = 0.f;

    const u32 kldb[2] = { sb + SMB_K0 + lr * QK_STB + lm * 16,
                          sb + SMB_K1 + lr * QK_STB + lm * 16 };
    const u32 vldb[2] = { sb + SMB_V0 + lr * VT_STB + lm * 16,
                          sb + SMB_V1 + lr * VT_STB + lm * 16 };

    for (int kt = 0; kt < NTILE; ++kt) {
        const int cb = kt & 1, nb = cb ^ 1;
        const bool more = (kt + 1 < NTILE);

        // prefetch next K/V into the other buffer
        if (more) {
            const int k0 = (kt + 1) * 128;
            const u32 kdst = sb + (nb ? SMB_K1 : SMB_K0);
            const u32 vdst = sb + (nb ? SMB_V1 : SMB_V0);
            #pragma unroll
            for (int j = 0; j < 4; ++j) {
                int idx = tid + j * 128;
                int row = idx >> 2, col = idx & 3;
                CP16(kdst + row * QK_STB + col * 16, gkb + (size_t)(k0 + row) * CC2 + col * 8);
            }
            #pragma unroll
            for (int j = 0; j < 8; ++j) {
                int idx = tid + j * 128;
                int row = idx >> 4, col = idx & 15;
                CP16(vdst + row * VT_STB + col * 16, gvb + (size_t)row * PP + k0 + col * 8);
            }
            CP_COMMIT();
        }

        const u32 kaddr = kldb[cb];
        const u32 vaddr = vldb[cb];

        __half2 hs[2][2];
        hs[0][0] = hs[0][1] = hs[1][0] = hs[1][1] = __floats2half2_rn(0.f, 0.f);

        // ---- per 32-key kp block: S (both row groups) then PV ----
        #pragma unroll
        for (int kp = 0; kp < 4; ++kp) {
            u32 kb[4][4];
            #pragma unroll
            for (int i = 0; i < 4; ++i)
                LDSM4(kb[i], kaddr + (kp * 4 + i) * 8 * QK_STB);

            u32 pf[2][4][2];
            #pragma unroll
            for (int i = 0; i < 4; ++i) {
                #pragma unroll
                for (int rg = 0; rg < 2; ++rg) {
                    u32 d[2] = {0u, 0u};
                    MMAF16H(d, aq[rg][0][0], aq[rg][0][1], aq[rg][0][2], aq[rg][0][3], kb[i][0], kb[i][1]);
                    MMAF16H(d, aq[rg][1][0], aq[rg][1][1], aq[rg][1][2], aq[rg][1][3], kb[i][2], kb[i][3]);
                    pf[rg][i][0] = h2_u32(h2exp2(u32_h2(d[0])));
                    pf[rg][i][1] = h2_u32(h2exp2(u32_h2(d[1])));
                }
            }

            // row-sum contributions (fma pipe)
            #pragma unroll
            for (int rg = 0; rg < 2; ++rg) {
                hs[rg][0] = __hadd2(__hadd2(hs[rg][0], u32_h2(pf[rg][0][0])),
                                    __hadd2(u32_h2(pf[rg][1][0]), u32_h2(pf[rg][2][0])));
                hs[rg][0] = __hadd2(hs[rg][0], u32_h2(pf[rg][3][0]));
                hs[rg][1] = __hadd2(__hadd2(hs[rg][1], u32_h2(pf[rg][0][1])),
                                    __hadd2(u32_h2(pf[rg][1][1]), u32_h2(pf[rg][2][1])));
                hs[rg][1] = __hadd2(hs[rg][1], u32_h2(pf[rg][3][1]));
            }

            // PV for this kp: 8 o-groups, vb just-in-time in pairs
            #pragma unroll
            for (int ng = 0; ng < 4; ++ng) {
                u32 vb[2][4];
                LDSM4(vb[0], vaddr + (2 * ng    ) * 8 * VT_STB + kp * 64);
                LDSM4(vb[1], vaddr + (2 * ng + 1) * 8 * VT_STB + kp * 64);
                #pragma unroll
                for (int rg = 0; rg < 2; ++rg) {
                    MMAF16(o[rg][2*ng],   pf[rg][0][0], pf[rg][0][1], pf[rg][1][0], pf[rg][1][1], vb[0][0], vb[0][1]);
                    MMAF16(o[rg][2*ng],   pf[rg][2][0], pf[rg][2][1], pf[rg][3][0], pf[rg][3][1], vb[0][2], vb[0][3]);
                    MMAF16(o[rg][2*ng+1], pf[rg][0][0], pf[rg][0][1], pf[rg][1][0], pf[rg][1][1], vb[1][0], vb[1][1]);
                    MMAF16(o[rg][2*ng+1], pf[rg][2][0], pf[rg][2][1], pf[rg][3][0], pf[rg][3][1], vb[1][2], vb[1][3]);
                }
            }
        }

        // fold tile sums into f32
        #pragma unroll
        for (int rg = 0; rg < 2; ++rg) {
            float2 fl = __half22float2(hs[rg][0]);
            float2 fh = __half22float2(hs[rg][1]);
            lsum[rg][0] += fl.x + fl.y;
            lsum[rg][1] += fh.x + fh.y;
        }

        CP_WAIT0();
        __syncthreads();
    }

    // ---- quad-reduce row sums, normalize, transpose via smem ----
    float* ot = (float*)smem;
    #pragma unroll
    for (int rg = 0; rg < 2; ++rg) {
        float slo = lsum[rg][0], shi = lsum[rg][1];
        slo += __shfl_xor_sync(0xffffffffu, slo, 1);
        slo += __shfl_xor_sync(0xffffffffu, slo, 2);
        shi += __shfl_xor_sync(0xffffffffu, shi, 1);
        shi += __shfl_xor_sync(0xffffffffu, shi, 2);
        const float inv_lo = 1.f / slo, inv_hi = 1.f / shi;
        const int prow = w * 32 + rg * 16 + g;
        #pragma unroll
        for (int nf2 = 0; nf2 < 8; ++nf2) {
            int oc = nf2 * 8 + 2 * tq;
            ot[(oc    ) * OT_S + prow    ] = o[rg][nf2][0] * inv_lo;
            ot[(oc + 1) * OT_S + prow    ] = o[rg][nf2][1] * inv_lo;
            ot[(oc    ) * OT_S + prow + 8] = o[rg][nf2][2] * inv_hi;
            ot[(oc + 1) * OT_S + prow + 8] = o[rg][nf2][3] * inv_hi;
        }
    }
    __syncthreads();

    // out[b, o, t, q0 + p] = O^T + residual (coalesced float4)
    {
        const int oc = tid >> 1, qt = tid & 1;
        const size_t gb = ((size_t)(b * CC + oc) * TT + t) * PP + q0 + qt * 64;
        const float* src = &ot[oc * OT_S + qt * 64];
        #pragma unroll
        for (int j = 0; j < 16; ++j) {
            float4 v = *(const float4*)&src[4 * j];
            float4 x = *(const float4*)&x_in[gb + 4 * j];
            v.x += x.x; v.y += x.y; v.z += x.z; v.w += x.w;
            *(float4*)&out[gb + 4 * j] = v;
        }
    }
}

// ---------------------------------------------------------------------------

extern "C" void kernel_launch(void* const* d_in, const int* in_sizes, int n_in,
                              void* d_out, int out_size) {
    const float* x_in = (const float*)d_in[0];
    const float* thw  = (const float*)d_in[1];
    const float* phw  = (const float*)d_in[2];
    const float* ow   = (const float*)d_in[3];
    float* out = (float*)d_out;

    const int prep_smem  = 2 * CC * XS_S * 4;  // 67584 B
    const int flash_smem = SMB_END;            // 65536 B

    cudaFuncSetAttribute(prep_kernel,  cudaFuncAttributeMaxDynamicSharedMemorySize, prep_smem);
    cudaFuncSetAttribute(flash_kernel, cudaFuncAttributeMaxDynamicSharedMemorySize, flash_smem);

    prep_kernel<<<dim3(NBT, PP / 128), 256, prep_smem>>>(x_in, thw, phw, ow);
    flash_kernel<<<dim3(PP / 128, NBT), 128, flash_smem>>>(x_in, out);
}

// round 17
// speedup vs baseline: 1.5889x; 1.0312x over previous
#include <cuda_runtime.h>
#include <cuda_fp16.h>
#include <cstdint>

#define CC    64
#define CC2   32
#define TT    8
#define PP    2304
#define NBT   16
#define NTILE 18
#define VROWS 64

typedef unsigned int u32;

__device__ __half g_q [NBT * PP * CC2];      // theta * scale * log2e, [bt][p][32]
__device__ __half g_k [NBT * PP * CC2];      // phi,                  [bt][p][32]
__device__ __half g_vt[NBT * VROWS * PP];    // (out_w @ x)^T, [bt][o][p]

__device__ __forceinline__ u32 smem_u32(const void* p){
    u32 a; asm("{ .reg .u64 t; cvta.to.shared.u64 t, %1; cvt.u32.u64 %0, t; }":"=r"(a):"l"(p)); return a;
}

#define LDSM4(r, a) \
    asm volatile("ldmatrix.sync.aligned.m8n8.x4.shared.b16 {%0,%1,%2,%3}, [%4];" \
        : "=r"((r)[0]),"=r"((r)[1]),"=r"((r)[2]),"=r"((r)[3]) : "r"(a))

#define MMAF16(d, a0, a1, a2, a3, b0, b1) \
    asm volatile("mma.sync.aligned.m16n8k16.row.col.f32.f16.f16.f32 " \
        "{%0,%1,%2,%3}, {%4,%5,%6,%7}, {%8,%9}, {%0,%1,%2,%3};" \
        : "+f"((d)[0]),"+f"((d)[1]),"+f"((d)[2]),"+f"((d)[3]) \
        : "r"(a0),"r"(a1),"r"(a2),"r"(a3), "r"(b0),"r"(b1))

#define MMAF16H(d, a0, a1, a2, a3, b0, b1) \
    asm volatile("mma.sync.aligned.m16n8k16.row.col.f16.f16.f16.f16 " \
        "{%0,%1}, {%2,%3,%4,%5}, {%6,%7}, {%0,%1};" \
        : "+r"((d)[0]),"+r"((d)[1]) \
        : "r"(a0),"r"(a1),"r"(a2),"r"(a3), "r"(b0),"r"(b1))

#define CP16(dst, src) \
    asm volatile("cp.async.cg.shared.global [%0], [%1], 16;" :: "r"(dst), "l"(src))
#define CP_COMMIT() asm volatile("cp.async.commit_group;" ::: "memory")
#define CP_WAIT0()  asm volatile("cp.async.wait_group 0;" ::: "memory")

__device__ __forceinline__ u32 h2_u32(__half2 h){ return *(u32*)&h; }
__device__ __forceinline__ __half2 u32_h2(u32 v){ return *(__half2*)&v; }

// ---------------------------------------------------------------------------
// Kernel A: per-(b,t) projections, 8x8 outer-product register tiles (FFMA
// roofline). out_w folded into V; V transposed [o][p]. grid (16,18), 256 thr.
// ---------------------------------------------------------------------------
#define XS_S 132
__global__ void __launch_bounds__(256)
prep_kernel(const float* __restrict__ x_in,
            const float* __restrict__ thw,
            const float* __restrict__ phw,
            const float* __restrict__ ow) {
    extern __shared__ float sm[];
    float* xs = sm;               // [64][132]
    float* wt = sm + CC * XS_S;   // [64][132]

    const int bt = blockIdx.x, b = bt >> 3, t = bt & 7;
    const int p0g = blockIdx.y * 128;
    const int tid = threadIdx.x;

    for (int i = tid; i < CC * 128; i += 256) {
        int c = i >> 7, pl = i & 127;
        xs[c * XS_S + pl] = x_in[((b * CC + c) * TT + t) * PP + p0g + pl];
    }
    for (int i = tid; i < CC2 * CC; i += 256) {
        int o = i >> 6, c = i & 63;
        wt[c * XS_S + o]      = thw[t * CC2 * CC + i];
        wt[c * XS_S + 32 + o] = phw[t * CC2 * CC + i];
    }
    for (int i = tid; i < CC * CC; i += 256) {
        int o = i >> 6, c = i & 63;
        wt[c * XS_S + 64 + o] = ow[i];
    }
    __syncthreads();

    const int r0 = (tid >> 4) << 3;
    const int p0 = (tid & 15) << 3;

    float acc[8][8];
    #pragma unroll
    for (int u = 0; u < 8; ++u)
        #pragma unroll
        for (int j = 0; j < 8; ++j) acc[u][j] = 0.f;

    #pragma unroll 4
    for (int c = 0; c < CC; ++c) {
        float4 w0 = *(float4*)&wt[c * XS_S + r0];
        float4 w1 = *(float4*)&wt[c * XS_S + r0 + 4];
        float4 x0 = *(float4*)&xs[c * XS_S + p0];
        float4 x1 = *(float4*)&xs[c * XS_S + p0 + 4];
        float wv[8] = {w0.x,w0.y,w0.z,w0.w,w1.x,w1.y,w1.z,w1.w};
        float xv[8] = {x0.x,x0.y,x0.z,x0.w,x1.x,x1.y,x1.z,x1.w};
        #pragma unroll
        for (int u = 0; u < 8; ++u)
            #pragma unroll
            for (int j = 0; j < 8; ++j)
                acc[u][j] = fmaf(wv[u], xv[j], acc[u][j]);
    }

    const float s2 = 0.17677669529663689f * 1.4426950408889634f;

    if (r0 < CC2) {
        #pragma unroll
        for (int j = 0; j < 8; ++j) {
            uint4 hv;
            hv.x = h2_u32(__floats2half2_rn(acc[0][j]*s2, acc[1][j]*s2));
            hv.y = h2_u32(__floats2half2_rn(acc[2][j]*s2, acc[3][j]*s2));
            hv.z = h2_u32(__floats2half2_rn(acc[4][j]*s2, acc[5][j]*s2));
            hv.w = h2_u32(__floats2half2_rn(acc[6][j]*s2, acc[7][j]*s2));
            *(uint4*)&g_q[((size_t)bt * PP + p0g + p0 + j) * CC2 + r0] = hv;
        }
    } else if (r0 < 2 * CC2) {
        #pragma unroll
        for (int j = 0; j < 8; ++j) {
            uint4 hv;
            hv.x = h2_u32(__floats2half2_rn(acc[0][j], acc[1][j]));
            hv.y = h2_u32(__floats2half2_rn(acc[2][j], acc[3][j]));
            hv.z = h2_u32(__floats2half2_rn(acc[4][j], acc[5][j]));
            hv.w = h2_u32(__floats2half2_rn(acc[6][j], acc[7][j]));
            *(uint4*)&g_k[((size_t)bt * PP + p0g + p0 + j) * CC2 + r0 - CC2] = hv;
        }
    } else {
        #pragma unroll
        for (int u = 0; u < 8; ++u) {
            uint4 hv;
            hv.x = h2_u32(__floats2half2_rn(acc[u][0], acc[u][1]));
            hv.y = h2_u32(__floats2half2_rn(acc[u][2], acc[u][3]));
            hv.z = h2_u32(__floats2half2_rn(acc[u][4], acc[u][5]));
            hv.w = h2_u32(__floats2half2_rn(acc[u][6], acc[u][7]));
            *(uint4*)&g_vt[((size_t)bt * VROWS + r0 - 2 * CC2 + u) * PP + p0g + p0] = hv;
        }
    }
}

// ---------------------------------------------------------------------------
// Kernel B: flash attention with IN-CTA KEY SPLIT. 256 threads, M=128,
// warps 0-3 process even key-tiles, warps 4-7 odd key-tiles (9 each);
// partial (O, lsum) are linear (no max subtraction) -> combined via smem at
// the end. grid (18,16)=288, launch_bounds(256,2) -> 2 CTAs/SM = 16 warps.
// 32 q-rows per warp (traffic-efficient shape).
// smem (unpadded + XOR swizzle): Q 64B-rows @0 (8192) | K[4] 64B-rows
// @8192 (4x8192) | V[4] 256B-rows @40960 (4x16384). total 106496.
// Swizzles: Q/K chunk' = c ^ ((row>>1)&3); V chunk' = c ^ (row&7).
// ---------------------------------------------------------------------------
#define SMB_END 106496
#define OT_S    132
#define SCR_S   67

__global__ void __launch_bounds__(256, 2)
flash_kernel(const float* __restrict__ x_in, float* __restrict__ out) {
    extern __shared__ char smem[];
    const u32 sb  = smem_u32(smem);
    const int tid  = threadIdx.x;
    const int w    = tid >> 5, lane = tid & 31;
    const int grp  = w >> 2;                       // key-parity group
    const int w4   = w & 3;                        // warp within group
    const int g    = lane >> 2, tq = lane & 3;
    const int lm   = lane >> 3, lr = lane & 7;
    const int bt   = blockIdx.y, b = bt >> 3, t = bt & 7;
    const int q0   = blockIdx.x * 128;

    const __half* gqb = &g_q[(size_t)bt * PP * CC2];
    const __half* gkb = &g_k[(size_t)bt * PP * CC2];
    const __half* gvb = &g_vt[(size_t)bt * VROWS * PP];

    // ---- prologue: Q + tiles 0,1 (phase 0) ----
    {
        #pragma unroll
        for (int j = 0; j < 2; ++j) {
            int idx = tid + j * 256;                 // 512 Q chunks
            int row = idx >> 2, c = idx & 3;
            u32 dst = sb + row * 64 + ((c ^ ((row >> 1) & 3)) << 4);
            CP16(dst, gqb + (size_t)(q0 + row) * CC2 + c * 8);
        }
        #pragma unroll
        for (int j = 0; j < 4; ++j) {
            int idx = tid + j * 256;                 // 1024 K chunks (2 tiles)
            int tile = idx >> 9, rem = idx & 511;
            int row = rem >> 2, c = rem & 3;
            u32 dst = sb + 8192 + (tile * 2) * 8192 + row * 64 + ((c ^ ((row >> 1) & 3)) << 4);
            CP16(dst, gkb + (size_t)(tile * 128 + row) * CC2 + c * 8);
        }
        #pragma unroll
        for (int j = 0; j < 8; ++j) {
            int idx = tid + j * 256;                 // 2048 V chunks (2 tiles)
            int tile = idx >> 10, rem = idx & 1023;
            int row = rem >> 4, c = rem & 15;
            u32 dst = sb + 40960 + (tile * 2) * 16384 + row * 256 + ((c ^ (row & 7)) << 4);
            CP16(dst, gvb + (size_t)row * PP + tile * 128 + c * 8);
        }
    }
    CP_COMMIT(); CP_WAIT0();
    __syncthreads();

    // Q A-fragments: 2 row groups (rows w4*32 and w4*32+16)
    u32 aq[2][2][4];
    #pragma unroll
    for (int rg = 0; rg < 2; ++rg) {
        const int qrow = w4 * 32 + rg * 16 + ((lm & 1) << 3) + lr;
        const int sw = (lr >> 1) & 3;
        LDSM4(aq[rg][0], sb + qrow * 64 + ((((lm >> 1)    ) ^ sw) << 4));
        LDSM4(aq[rg][1], sb + qrow * 64 + ((((lm >> 1) + 2) ^ sw) << 4));
    }

    float o[2][8][4];
    #pragma unroll
    for (int rg = 0; rg < 2; ++rg)
        #pragma unroll
        for (int i = 0; i < 8; ++i)
            #pragma unroll
            for (int j = 0; j < 4; ++j) o[rg][i][j] = 0.f;
    float lsum[2][2];
    lsum[0][0] = lsum[0][1] = lsum[1][0] = lsum[1][1] = 0.f;

    for (int s = 0; s < 9; ++s) {
        const int ph = s & 1;

        // prefetch tiles 2(s+1), 2(s+1)+1 into phase ph^1
        if (s < 8) {
            const int kt0 = 2 * (s + 1);
            #pragma unroll
            for (int j = 0; j < 4; ++j) {
                int idx = tid + j * 256;
                int tile = idx >> 9, rem = idx & 511;
                int row = rem >> 2, c = rem & 3;
                u32 dst = sb + 8192 + (tile * 2 + (ph ^ 1)) * 8192 + row * 64 + ((c ^ ((row >> 1) & 3)) << 4);
                CP16(dst, gkb + (size_t)((kt0 + tile) * 128 + row) * CC2 + c * 8);
            }
            #pragma unroll
            for (int j = 0; j < 8; ++j) {
                int idx = tid + j * 256;
                int tile = idx >> 10, rem = idx & 1023;
                int row = rem >> 4, c = rem & 15;
                u32 dst = sb + 40960 + (tile * 2 + (ph ^ 1)) * 16384 + row * 256 + ((c ^ (row & 7)) << 4);
                CP16(dst, gvb + (size_t)row * PP + (kt0 + tile) * 128 + c * 8);
            }
            CP_COMMIT();
        }

        // compute on this group's tile (grp, ph)
        const u32 kaddr = sb + 8192  + (grp * 2 + ph) * 8192 + lr * 64 + ((lm ^ ((lr >> 1) & 3)) << 4);
        const u32 vbase = sb + 40960 + (grp * 2 + ph) * 16384 + lr * 256;

        __half2 hs[2][2];
        hs[0][0] = hs[0][1] = hs[1][0] = hs[1][1] = __floats2half2_rn(0.f, 0.f);

        #pragma unroll
        for (int kp = 0; kp < 4; ++kp) {
            u32 pf[2][4][2];
            #pragma unroll
            for (int ih = 0; ih < 2; ++ih) {
                u32 kb[2][4];
                LDSM4(kb[0], kaddr + (kp * 4 + ih * 2    ) * 512);
                LDSM4(kb[1], kaddr + (kp * 4 + ih * 2 + 1) * 512);
                #pragma unroll
                for (int i2 = 0; i2 < 2; ++i2) {
                    #pragma unroll
                    for (int rg = 0; rg < 2; ++rg) {
                        u32 d[2] = {0u, 0u};
                        MMAF16H(d, aq[rg][0][0], aq[rg][0][1], aq[rg][0][2], aq[rg][0][3], kb[i2][0], kb[i2][1]);
                        MMAF16H(d, aq[rg][1][0], aq[rg][1][1], aq[rg][1][2], aq[rg][1][3], kb[i2][2], kb[i2][3]);
                        pf[rg][ih * 2 + i2][0] = h2_u32(h2exp2(u32_h2(d[0])));
                        pf[rg][ih * 2 + i2][1] = h2_u32(h2exp2(u32_h2(d[1])));
                    }
                }
            }

            // row-sum contributions (fma pipe)
            #pragma unroll
            for (int rg = 0; rg < 2; ++rg) {
                hs[rg][0] = __hadd2(__hadd2(hs[rg][0], u32_h2(pf[rg][0][0])),
                                    __hadd2(u32_h2(pf[rg][1][0]), u32_h2(pf[rg][2][0])));
                hs[rg][0] = __hadd2(hs[rg][0], u32_h2(pf[rg][3][0]));
                hs[rg][1] = __hadd2(__hadd2(hs[rg][1], u32_h2(pf[rg][0][1])),
                                    __hadd2(u32_h2(pf[rg][1][1]), u32_h2(pf[rg][2][1])));
                hs[rg][1] = __hadd2(hs[rg][1], u32_h2(pf[rg][3][1]));
            }

            // PV for this kp: 8 o-groups (o[2ng] = V rows 16ng.., o[2ng+1] = +8)
            #pragma unroll
            for (int ng = 0; ng < 4; ++ng) {
                u32 vb[2][4];
                const u32 va = vbase + ng * 4096;
                LDSM4(vb[0], va        + ((((kp << 2) | lm) ^ lr) << 4));
                LDSM4(vb[1], va + 2048 + ((((kp << 2) | lm) ^ lr) << 4));
                #pragma unroll
                for (int rg = 0; rg < 2; ++rg) {
                    MMAF16(o[rg][2*ng],   pf[rg][0][0], pf[rg][0][1], pf[rg][1][0], pf[rg][1][1], vb[0][0], vb[0][1]);
                    MMAF16(o[rg][2*ng],   pf[rg][2][0], pf[rg][2][1], pf[rg][3][0], pf[rg][3][1], vb[0][2], vb[0][3]);
                    MMAF16(o[rg][2*ng+1], pf[rg][0][0], pf[rg][0][1], pf[rg][1][0], pf[rg][1][1], vb[1][0], vb[1][1]);
                    MMAF16(o[rg][2*ng+1], pf[rg][2][0], pf[rg][2][1], pf[rg][3][0], pf[rg][3][1], vb[1][2], vb[1][3]);
                }
            }
        }

        // fold tile sums into f32
        #pragma unroll
        for (int rg = 0; rg < 2; ++rg) {
            float2 fl = __half22float2(hs[rg][0]);
            float2 fh = __half22float2(hs[rg][1]);
            lsum[rg][0] += fl.x + fl.y;
            lsum[rg][1] += fh.x + fh.y;
        }

        CP_WAIT0();
        __syncthreads();
    }

    // ---- combine the two key-halves (linear: just add partials) ----
    float* scr  = (float*)smem;                        // [128][67]
    float* scrL = (float*)(smem + 128 * SCR_S * 4);    // [128][4]
    if (grp == 1) {
        const int tt = tid - 128;
        #pragma unroll
        for (int rg = 0; rg < 2; ++rg)
            #pragma unroll
            for (int i = 0; i < 8; ++i)
                #pragma unroll
                for (int j = 0; j < 4; ++j)
                    scr[tt * SCR_S + rg * 32 + i * 4 + j] = o[rg][i][j];
        scrL[tt * 4 + 0] = lsum[0][0]; scrL[tt * 4 + 1] = lsum[0][1];
        scrL[tt * 4 + 2] = lsum[1][0]; scrL[tt * 4 + 3] = lsum[1][1];
    }
    __syncthreads();
    if (grp == 0) {
        #pragma unroll
        for (int rg = 0; rg < 2; ++rg)
            #pragma unroll
            for (int i = 0; i < 8; ++i)
                #pragma unroll
                for (int j = 0; j < 4; ++j)
                    o[rg][i][j] += scr[tid * SCR_S + rg * 32 + i * 4 + j];
        lsum[0][0] += scrL[tid * 4 + 0]; lsum[0][1] += scrL[tid * 4 + 1];
        lsum[1][0] += scrL[tid * 4 + 2]; lsum[1][1] += scrL[tid * 4 + 3];
    }
    __syncthreads();   // all scr reads done before ot overwrites the region

    float* ot = (float*)smem;   // [64][132]
    if (grp == 0) {
        #pragma unroll
        for (int rg = 0; rg < 2; ++rg) {
            float slo = lsum[rg][0], shi = lsum[rg][1];
            slo += __shfl_xor_sync(0xffffffffu, slo, 1);
            slo += __shfl_xor_sync(0xffffffffu, slo, 2);
            shi += __shfl_xor_sync(0xffffffffu, shi, 1);
            shi += __shfl_xor_sync(0xffffffffu, shi, 2);
            const float inv_lo = 1.f / slo, inv_hi = 1.f / shi;
            const int prow = w4 * 32 + rg * 16 + g;
            #pragma unroll
            for (int i = 0; i < 8; ++i) {
                int oc = i * 8 + 2 * tq;
                ot[(oc    ) * OT_S + prow    ] = o[rg][i][0] * inv_lo;
                ot[(oc + 1) * OT_S + prow    ] = o[rg][i][1] * inv_lo;
                ot[(oc    ) * OT_S + prow + 8] = o[rg][i][2] * inv_hi;
                ot[(oc + 1) * OT_S + prow + 8] = o[rg][i][3] * inv_hi;
            }
        }
    }
    __syncthreads();

    // out[b, o, t, q0 + p] = O^T + residual (coalesced float4, 256 threads)
    {
        const int oc = tid >> 2, qt = tid & 3;
        const size_t gb = ((size_t)(b * CC + oc) * TT + t) * PP + q0 + qt * 32;
        const float* src = &ot[oc * OT_S + qt * 32];
        #pragma unroll
        for (int j = 0; j < 8; ++j) {
            float4 v = *(const float4*)&src[4 * j];
            float4 x = *(const float4*)&x_in[gb + 4 * j];
            v.x += x.x; v.y += x.y; v.z += x.z; v.w += x.w;
            *(float4*)&out[gb + 4 * j] = v;
        }
    }
}

// ---------------------------------------------------------------------------

extern "C" void kernel_launch(void* const* d_in, const int* in_sizes, int n_in,
                              void* d_out, int out_size) {
    const float* x_in = (const float*)d_in[0];
    const float* thw  = (const float*)d_in[1];
    const float* phw  = (const float*)d_in[2];
    const float* ow   = (const float*)d_in[3];
    float* out = (float*)d_out;

    const int prep_smem  = 2 * CC * XS_S * 4;  // 67584 B
    const int flash_smem = SMB_END;            // 106496 B

    cudaFuncSetAttribute(prep_kernel,  cudaFuncAttributeMaxDynamicSharedMemorySize, prep_smem);
    cudaFuncSetAttribute(flash_kernel, cudaFuncAttributeMaxDynamicSharedMemorySize, flash_smem);

    prep_kernel<<<dim3(NBT, PP / 128), 256, prep_smem>>>(x_in, thw, phw, ow);
    flash_kernel<<<dim3(PP / 128, NBT), 256, flash_smem>>>(x_in, out);
}